// round 2
// baseline (speedup 1.0000x reference)
#include <cuda_runtime.h>

// TranslateCube: out(y,x) = bilinear sample of in at (y - ty, x - tx), zero fill.
// [B*T, 256, 256] fp32; (tx, ty) constant per image.
//
// Key trick: ty is constant per image, so y0(row r+1) == y0(row r) + 1 in
// nearly every case -> the bottom-corner loads of iteration r are the
// top-corner loads of iteration r+1. Cache them in registers, halving LDG
// count. The per-row floorf(y - ty) is kept bit-identical to the reference;
// reuse is guarded by an explicit (warp-uniform) y0 continuity check.

#define HH 256
#define WW 256
#define ROWS_PER_BLOCK 16

__global__ __launch_bounds__(256) void translate_kernel(
    const float* __restrict__ img,
    const float* __restrict__ dx,
    const float* __restrict__ dy,
    float* __restrict__ out)
{
    const int imgIdx = blockIdx.y;
    const int yBase  = blockIdx.x * ROWS_PER_BLOCK;
    const float tx = __ldg(dx + imgIdx);
    const float ty = __ldg(dy + imgIdx);

    const int x = threadIdx.x;
    // Per-column source coordinate (constant across rows for this thread)
    const float sx  = (float)x - tx;
    const float x0f = floorf(sx);
    const float wx  = sx - x0f;
    const int   x0  = (int)x0f;
    const bool  vx0 = (x0 >= 0)     && (x0 <= WW - 1);
    const bool  vx1 = (x0 + 1 >= 0) && (x0 + 1 <= WW - 1);

    const float* base  = img + (size_t)imgIdx * (HH * WW);
    float*       obase = out + (size_t)imgIdx * (HH * WW);

    // Register cache of the previous iteration's bottom-row corner values.
    float pb0 = 0.0f, pb1 = 0.0f;
    int prev_y0 = -0x40000000;

    #pragma unroll
    for (int r = 0; r < ROWS_PER_BLOCK; ++r) {
        const int y = yBase + r;
        const float sy  = (float)y - ty;
        const float y0f = floorf(sy);
        const float wy  = sy - y0f;
        const int   y0  = (int)y0f;
        const bool  vy0 = (y0 >= 0)     && (y0 <= HH - 1);
        const bool  vy1 = (y0 + 1 >= 0) && (y0 + 1 <= HH - 1);

        float a0, a1;
        if (y0 == prev_y0 + 1) {            // warp-uniform branch
            a0 = pb0; a1 = pb1;             // reuse last iteration's bottom row
        } else {
            const float* row0 = base + (long)y0 * WW;
            a0 = (vy0 && vx0) ? __ldg(row0 + x0)     : 0.0f;
            a1 = (vy0 && vx1) ? __ldg(row0 + x0 + 1) : 0.0f;
        }
        const float* row1 = base + (long)(y0 + 1) * WW;
        const float b0 = (vy1 && vx0) ? __ldg(row1 + x0)     : 0.0f;
        const float b1 = (vy1 && vx1) ? __ldg(row1 + x0 + 1) : 0.0f;

        const float top = fmaf(wx, a1 - a0, a0);
        const float bot = fmaf(wx, b1 - b0, b0);
        __stcs(obase + (size_t)y * WW + x, fmaf(wy, bot - top, top));

        pb0 = b0; pb1 = b1; prev_y0 = y0;
    }
}

extern "C" void kernel_launch(void* const* d_in, const int* in_sizes, int n_in,
                              void* d_out, int out_size) {
    const float* images = (const float*)d_in[0];
    const float* dx     = (const float*)d_in[1];
    const float* dy     = (const float*)d_in[2];
    // d_in[3] is winsize (unused by the math)
    float* out = (float*)d_out;

    const int n_images = in_sizes[1];  // B*T (dx element count)

    dim3 grid(HH / ROWS_PER_BLOCK, n_images);
    translate_kernel<<<grid, 256>>>(images, dx, dy, out);
}

// round 3
// speedup vs baseline: 1.4567x; 1.4567x over previous
#include <cuda_runtime.h>

// TranslateCube: out(y,x) = bilinear sample of in at (y - ty, x - tx), zero fill.
// [B*T, 256, 256] fp32; (tx, ty) constant per image.
//
// Each thread produces 4 consecutive pixels of one output row:
//   - source columns overlap: only 5 loads per input row per 4 pixels
//   - one aligned float4 store per 4 pixels
//   - all loads independent across rows/iterations -> high MLP (R2 lesson)

#define HH 256
#define WW 256
#define PX 4                 // pixels per thread (x)
#define CGRP (WW / PX)       // 64 column groups
#define RY 4                 // rows covered by blockDim.y
#define ROWS_PER_BLOCK 8     // rows per block (RY * 2 loop iterations)

__global__ __launch_bounds__(256) void translate_kernel(
    const float* __restrict__ img,
    const float* __restrict__ dx,
    const float* __restrict__ dy,
    float* __restrict__ out)
{
    const int imgIdx = blockIdx.y;
    const int yBase  = blockIdx.x * ROWS_PER_BLOCK + threadIdx.y;
    const float tx = __ldg(dx + imgIdx);
    const float ty = __ldg(dy + imgIdx);

    const int c = threadIdx.x;      // column group 0..63
    const int x = c * PX;           // first output column

    // Shared integer base column for the 4 pixels; per-pixel fractional
    // weights computed from the reference's exact fp32 expression.
    const float sx0 = (float)x - tx;
    const int   x0  = (int)floorf(sx0);

    float wx[PX];
    bool  vx[PX + 1];
    #pragma unroll
    for (int j = 0; j < PX; ++j)
        wx[j] = ((float)(x + j) - tx) - (float)(x0 + j);
    #pragma unroll
    for (int j = 0; j <= PX; ++j)
        vx[j] = (x0 + j >= 0) && (x0 + j <= WW - 1);

    const float* base  = img + (size_t)imgIdx * (HH * WW);
    float4*      obase = (float4*)(out + (size_t)imgIdx * (HH * WW));

    #pragma unroll
    for (int k = 0; k < ROWS_PER_BLOCK / RY; ++k) {
        const int y = yBase + k * RY;
        const float sy  = (float)y - ty;
        const float y0f = floorf(sy);
        const float wy  = sy - y0f;
        const int   y0  = (int)y0f;
        const bool  vy0 = (y0 >= 0)     && (y0 <= HH - 1);
        const bool  vy1 = (y0 + 1 >= 0) && (y0 + 1 <= HH - 1);

        const float* row0 = base + (long)y0 * WW + x0;
        const float* row1 = row0 + WW;

        float a[PX + 1], b[PX + 1];
        #pragma unroll
        for (int j = 0; j <= PX; ++j) {
            a[j] = (vy0 && vx[j]) ? __ldg(row0 + j) : 0.0f;
            b[j] = (vy1 && vx[j]) ? __ldg(row1 + j) : 0.0f;
        }

        float o[PX];
        #pragma unroll
        for (int j = 0; j < PX; ++j) {
            const float top = fmaf(wx[j], a[j + 1] - a[j], a[j]);
            const float bot = fmaf(wx[j], b[j + 1] - b[j], b[j]);
            o[j] = fmaf(wy, bot - top, top);
        }
        obase[y * CGRP + c] = make_float4(o[0], o[1], o[2], o[3]);
    }
}

extern "C" void kernel_launch(void* const* d_in, const int* in_sizes, int n_in,
                              void* d_out, int out_size) {
    const float* images = (const float*)d_in[0];
    const float* dx     = (const float*)d_in[1];
    const float* dy     = (const float*)d_in[2];
    // d_in[3] is winsize (unused by the math)
    float* out = (float*)d_out;

    const int n_images = in_sizes[1];  // B*T (dx element count)

    dim3 block(CGRP, RY);              // 64 x 4 = 256 threads
    dim3 grid(HH / ROWS_PER_BLOCK, n_images);
    translate_kernel<<<grid, block>>>(images, dx, dy, out);
}